// round 16
// baseline (speedup 1.0000x reference)
#include <cuda_runtime.h>
#include <cstdint>
#include <cstddef>

#define BATCH 256
#define SEQ   512
#define HID   256
#define G3    768
#define IN_DIM 65
#define RDIM  64

#define OUT_N  ((size_t)BATCH * SEQ * RDIM)
#define HID_N  ((size_t)BATCH * SEQ * HID)
#define TOT_N  (OUT_N + HID_N)

__device__ float g_gi [(size_t)BATCH * SEQ * G3];  // 402 MB scratch
__device__ float g_hid[HID_N];
__device__ float g_out[OUT_N];

// ---------------- helpers ----------------
__device__ __forceinline__ void ffma2(unsigned long long &acc,
                                      unsigned long long a, unsigned long long b) {
    asm("fma.rn.f32x2 %0, %1, %2, %0;" : "+l"(acc) : "l"(a), "l"(b));
}
__device__ __forceinline__ float f2sum(unsigned long long a) {
    unsigned int lo, hi;
    asm("mov.b64 {%0,%1}, %2;" : "=r"(lo), "=r"(hi) : "l"(a));
    return __uint_as_float(lo) + __uint_as_float(hi);
}
__device__ __forceinline__ float sigmoidf_(float x) {
    return __fdividef(1.0f, 1.0f + __expf(-x));
}

// =====================================================================
// Kernel 1: gi = stimulus @ W_ih^T + b_ih — R15 version (lane-swapped:
// w-loads broadcast 1 wf, x-loads 1 wf).
// =====================================================================
#define GI_TBT 16
#define GI_PITCH 70
#define GI_SMEM ((G3 * GI_PITCH + GI_TBT * GI_PITCH) * 4)

__global__ void __launch_bounds__(512, 1)
gi_kernel(const float* __restrict__ stim,
          const float* __restrict__ W_ih,
          const float* __restrict__ b_ih)
{
    extern __shared__ float sm[];
    float* w_s = sm;                    // [768][70]
    float* x_s = sm + G3 * GI_PITCH;    // [16][70]

    const int tid = threadIdx.x;
    const int bt0 = blockIdx.x * GI_TBT;

    for (int idx = tid; idx < G3 * IN_DIM; idx += 512) {
        int g = idx / IN_DIM, k = idx - g * IN_DIM;
        w_s[g * GI_PITCH + k] = W_ih[idx];
    }
    for (int idx = tid; idx < GI_TBT * IN_DIM; idx += 512) {
        int r = idx / IN_DIM, c = idx - r * IN_DIM;
        x_s[r * GI_PITCH + c] = stim[(size_t)(bt0 + r) * IN_DIM + c];
    }
    __syncthreads();

    const int gx = tid >> 3;        // 0..63  (4 distinct per warp -> bcast w)
    const int by = tid & 7;         // 0..7   (lane-varying -> distinct x rows)

    unsigned long long acc0[12], acc1[12];
#pragma unroll
    for (int i = 0; i < 12; ++i) { acc0[i] = 0ull; acc1[i] = 0ull; }

    const float* x0 = x_s + (by * 2) * GI_PITCH;
    const float* x1 = x_s + (by * 2 + 1) * GI_PITCH;

#pragma unroll 4
    for (int k = 0; k < 64; k += 2) {
        unsigned long long xv0 = *(const unsigned long long*)(x0 + k);
        unsigned long long xv1 = *(const unsigned long long*)(x1 + k);
#pragma unroll
        for (int i = 0; i < 12; ++i) {
            unsigned long long wv =
                *(const unsigned long long*)(w_s + (gx + 64 * i) * GI_PITCH + k);
            ffma2(acc0[i], xv0, wv);
            ffma2(acc1[i], xv1, wv);
        }
    }
    const float x0l = x0[64], x1l = x1[64];

    const size_t base0 = (size_t)(bt0 + by * 2) * G3;
    const size_t base1 = base0 + G3;
#pragma unroll
    for (int i = 0; i < 12; ++i) {
        int   g    = gx + 64 * i;
        float w64  = w_s[g * GI_PITCH + 64];
        float bias = b_ih[g];
        g_gi[base0 + g] = f2sum(acc0[i]) + x0l * w64 + bias;
        g_gi[base1 + g] = f2sum(acc1[i]) + x1l * w64 + bias;
    }
}

// probe: shifts the fixed ncu capture slot; placed AFTER gru this round.
__global__ void probe_kernel() {}

// =====================================================================
// Kernel 2: GRU — EXACT R7 version (best measured GRU; STG before arrive).
// =====================================================================
#define CLUSTER 4
#define HT 64
#define BT 8
#define WPITCH 260
#define HPITCH 260
#define GRU_SMEM ((3 * HT * WPITCH + 2 * BT * HPITCH) * 4)

__global__ void __cluster_dims__(CLUSTER, 1, 1) __launch_bounds__(256, 1)
gru_kernel(const float* __restrict__ W_hh,
           const float* __restrict__ b_hh,
           float* __restrict__ out_hid)
{
    extern __shared__ float smem[];
    float* Ws = smem;                   // [3][64][260]
    float* hs = smem + 3 * HT * WPITCH; // [2][8][260]

    const int tid = threadIdx.x;
    unsigned int rank;
    asm("mov.u32 %0, %%cluster_ctarank;" : "=r"(rank));
    const int cl     = blockIdx.x / CLUSTER;
    const int h_off  = (int)rank * HT;
    const int b_base = cl * BT;

    for (int idx = tid; idx < 3 * HT * HID; idx += 256) {
        int g   = idx >> 14;
        int rem = idx & 16383;
        int u   = rem >> 8;
        int k   = rem & 255;
        Ws[(g * HT + u) * WPITCH + k] = W_hh[((g * HID) + h_off + u) * HID + k];
    }
    for (int idx = tid; idx < BT * HID; idx += 256) {
        int b = idx >> 8, c = idx & 255;
        hs[b * HPITCH + c] = 0.1f;
    }
    __syncthreads();

    const int bx = tid & 3;
    const int u  = tid >> 2;
    const int b0 = 2 * bx, b1 = 2 * bx + 1;
    const int ug = h_off + u;

    const float bhr = b_hh[ug];
    const float bhz = b_hh[HID + ug];
    const float bhn = b_hh[2 * HID + ug];

    const float* gi0 = g_gi + (size_t)(b_base + b0) * SEQ * G3 + ug;
    const float* gi1 = g_gi + (size_t)(b_base + b1) * SEQ * G3 + ug;
    float* o0 = out_hid + (size_t)(b_base + b0) * SEQ * HID + ug;
    float* o1 = out_hid + (size_t)(b_base + b1) * SEQ * HID + ug;

    const unsigned int hs_u32 = (unsigned int)__cvta_generic_to_shared(hs);

    const float* w_r = Ws + (0 * HT + u) * WPITCH;
    const float* w_z = Ws + (1 * HT + u) * WPITCH;
    const float* w_n = Ws + (2 * HT + u) * WPITCH;

    int buf = 0;
    for (int t = 0; t < SEQ; ++t) {
        float gir0 = gi0[0], giz0 = gi0[HID], gin0 = gi0[2 * HID];
        float gir1 = gi1[0], giz1 = gi1[HID], gin1 = gi1[2 * HID];

        const float* hr0 = hs + (buf * BT + b0) * HPITCH;
        const float* hr1 = hs + (buf * BT + b1) * HPITCH;

        unsigned long long ar0 = 0, az0 = 0, an0 = 0;
        unsigned long long ar1 = 0, az1 = 0, an1 = 0;
#pragma unroll 8
        for (int k = 0; k < HID; k += 4) {
            ulonglong2 h0 = *(const ulonglong2*)(hr0 + k);
            ulonglong2 h1 = *(const ulonglong2*)(hr1 + k);
            ulonglong2 wr = *(const ulonglong2*)(w_r + k);
            ulonglong2 wz = *(const ulonglong2*)(w_z + k);
            ulonglong2 wn = *(const ulonglong2*)(w_n + k);
            ffma2(ar0, h0.x, wr.x); ffma2(ar0, h0.y, wr.y);
            ffma2(az0, h0.x, wz.x); ffma2(az0, h0.y, wz.y);
            ffma2(an0, h0.x, wn.x); ffma2(an0, h0.y, wn.y);
            ffma2(ar1, h1.x, wr.x); ffma2(ar1, h1.y, wr.y);
            ffma2(az1, h1.x, wz.x); ffma2(az1, h1.y, wz.y);
            ffma2(an1, h1.x, wn.x); ffma2(an1, h1.y, wn.y);
        }
        float sr0 = f2sum(ar0) + bhr, sz0 = f2sum(az0) + bhz, sn0 = f2sum(an0) + bhn;
        float sr1 = f2sum(ar1) + bhr, sz1 = f2sum(az1) + bhz, sn1 = f2sum(an1) + bhn;

        float h_old0 = hr0[ug];
        float h_old1 = hr1[ug];

        float r0 = sigmoidf_(gir0 + sr0);
        float z0 = sigmoidf_(giz0 + sz0);
        float n0 = fmaxf(fmaf(r0, sn0, gin0), 0.0f);
        float hn0 = fmaf(z0, h_old0 - n0, n0);      // (1-z)n + z*h

        float r1 = sigmoidf_(gir1 + sr1);
        float z1 = sigmoidf_(giz1 + sz1);
        float n1 = fmaxf(fmaf(r1, sn1, gin1), 0.0f);
        float hn1 = fmaf(z1, h_old1 - n1, n1);

        o0[0] = hn0;
        o1[0] = hn1;

        const int nbuf = buf ^ 1;
        unsigned int a0 = hs_u32 + (unsigned int)(((nbuf * BT + b0) * HPITCH + ug) * 4);
        unsigned int a1 = hs_u32 + (unsigned int)(((nbuf * BT + b1) * HPITCH + ug) * 4);
#pragma unroll
        for (int rr = 0; rr < CLUSTER; ++rr) {
            unsigned int ra0, ra1;
            asm("mapa.shared::cluster.u32 %0, %1, %2;" : "=r"(ra0) : "r"(a0), "r"(rr));
            asm("mapa.shared::cluster.u32 %0, %1, %2;" : "=r"(ra1) : "r"(a1), "r"(rr));
            asm volatile("st.shared::cluster.f32 [%0], %1;" :: "r"(ra0), "f"(hn0) : "memory");
            asm volatile("st.shared::cluster.f32 [%0], %1;" :: "r"(ra1), "f"(hn1) : "memory");
        }
        asm volatile("barrier.cluster.arrive.aligned;" ::: "memory");
        asm volatile("barrier.cluster.wait.aligned;"   ::: "memory");

        buf = nbuf;
        gi0 += G3; gi1 += G3; o0 += HID; o1 += HID;
    }
}

// =====================================================================
// Kernel 3: head — HD_TBT 64->32: SMEM 99,328 B -> 2 CTAs/SM (16 warps),
// fixing the measured occ=12.4% latency exposure. Same access pattern.
// =====================================================================
#define HD_TBT 32
#define HD_HPITCH 260
#define HD_WPITCH 258
#define HD_SMEM ((HD_TBT * HD_HPITCH + RDIM * HD_WPITCH) * 4)   // 99,328 B

__global__ void __launch_bounds__(256, 2)
head_kernel(const float* __restrict__ hid,
            const float* __restrict__ W_out,
            const float* __restrict__ b_out,
            float* __restrict__ out)
{
    extern __shared__ float sm[];
    float* h_s = sm;                      // [32][260]
    float* w_s = sm + HD_TBT * HD_HPITCH; // [64][258]

    const int tid = threadIdx.x;
    const int bt0 = blockIdx.x * HD_TBT;

    for (int idx = tid; idx < HD_TBT * HID; idx += 256) {
        int r = idx >> 8, c = idx & 255;
        h_s[r * HD_HPITCH + c] = hid[(size_t)(bt0 + r) * HID + c];
    }
    for (int idx = tid; idx < RDIM * HID; idx += 256) {
        int r = idx >> 8, c = idx & 255;
        w_s[r * HD_WPITCH + c] = W_out[idx];
    }
    __syncthreads();

    const int rx = tid & 15;   // r  = rx + 16*i, i < 4
    const int by = tid >> 4;   // bt = bt0 + by*2 + j, j < 2

    unsigned long long acc[2][4];
#pragma unroll
    for (int j = 0; j < 2; ++j)
#pragma unroll
        for (int i = 0; i < 4; ++i) acc[j][i] = 0ull;

#pragma unroll 4
    for (int k = 0; k < HID; k += 2) {
        unsigned long long hv[2], wv[4];
#pragma unroll
        for (int j = 0; j < 2; ++j)
            hv[j] = *(const unsigned long long*)(h_s + (by * 2 + j) * HD_HPITCH + k);
#pragma unroll
        for (int i = 0; i < 4; ++i)
            wv[i] = *(const unsigned long long*)(w_s + (rx + 16 * i) * HD_WPITCH + k);
#pragma unroll
        for (int j = 0; j < 2; ++j)
#pragma unroll
            for (int i = 0; i < 4; ++i) ffma2(acc[j][i], hv[j], wv[i]);
    }

#pragma unroll
    for (int j = 0; j < 2; ++j) {
        size_t row = (size_t)(bt0 + by * 2 + j) * RDIM;
#pragma unroll
        for (int i = 0; i < 4; ++i) {
            int   r = rx + 16 * i;
            float v = f2sum(acc[j][i]) + b_out[r];
            out[row + r] = fmaxf(v, 0.0f);
        }
    }
}

// =====================================================================
extern "C" void kernel_launch(void* const* d_in, const int* in_sizes, int n_in,
                              void* d_out, int out_size)
{
    const float *stim = nullptr, *W_ih = nullptr, *W_hh = nullptr,
                *b_ih = nullptr, *b_hh = nullptr, *W_out = nullptr, *b_out = nullptr;

    for (int i = 0; i < n_in; ++i) {
        const float* p = (const float*)d_in[i];
        switch (in_sizes[i]) {
            case BATCH * SEQ * IN_DIM: stim  = p; break;
            case G3 * IN_DIM:          W_ih  = p; break;
            case G3 * HID:             W_hh  = p; break;
            case RDIM * HID:           W_out = p; break;
            case RDIM:                 b_out = p; break;
            case G3:
                if (!b_ih) b_ih = p; else b_hh = p;
                break;
            default: break;
        }
    }
    if (!stim || !W_ih || !W_hh || !b_ih || !b_hh || !W_out || !b_out)
        return;

    float* g_hid_ptr;  cudaGetSymbolAddress((void**)&g_hid_ptr, g_hid);
    float* g_out_ptr;  cudaGetSymbolAddress((void**)&g_out_ptr, g_out);

    float* out;
    float* hid;
    if ((size_t)out_size >= TOT_N) {
        out = (float*)d_out;
        hid = (float*)d_out + OUT_N;
    } else if ((size_t)out_size >= HID_N) {
        hid = (float*)d_out;
        out = g_out_ptr;
    } else {
        out = (float*)d_out;
        hid = g_hid_ptr;
    }

    cudaFuncSetAttribute(gi_kernel,   cudaFuncAttributeMaxDynamicSharedMemorySize, GI_SMEM);
    cudaFuncSetAttribute(gru_kernel,  cudaFuncAttributeMaxDynamicSharedMemorySize, GRU_SMEM);
    cudaFuncSetAttribute(head_kernel, cudaFuncAttributeMaxDynamicSharedMemorySize, HD_SMEM);

    gi_kernel  <<<(BATCH * SEQ) / GI_TBT, 512, GI_SMEM>>>(stim, W_ih, b_ih);
    gru_kernel <<<(BATCH / BT) * CLUSTER, 256, GRU_SMEM>>>(W_hh, b_hh, hid);
    probe_kernel<<<1, 32>>>();   // shift ncu capture slot (aiming at gru/head)
    head_kernel<<<(BATCH * SEQ) / HD_TBT, 256, HD_SMEM>>>(hid, W_out, b_out, out);
}

// round 17
// speedup vs baseline: 1.0038x; 1.0038x over previous
#include <cuda_runtime.h>
#include <cstdint>
#include <cstddef>

#define BATCH 256
#define SEQ   512
#define HID   256
#define G3    768
#define IN_DIM 65
#define RDIM  64

#define OUT_N  ((size_t)BATCH * SEQ * RDIM)
#define HID_N  ((size_t)BATCH * SEQ * HID)
#define TOT_N  (OUT_N + HID_N)

__device__ float g_gi [(size_t)BATCH * SEQ * G3];  // 402 MB scratch
__device__ float g_hid[HID_N];
__device__ float g_out[OUT_N];

// ---------------- helpers ----------------
__device__ __forceinline__ void ffma2(unsigned long long &acc,
                                      unsigned long long a, unsigned long long b) {
    asm("fma.rn.f32x2 %0, %1, %2, %0;" : "+l"(acc) : "l"(a), "l"(b));
}
__device__ __forceinline__ float f2sum(unsigned long long a) {
    unsigned int lo, hi;
    asm("mov.b64 {%0,%1}, %2;" : "=r"(lo), "=r"(hi) : "l"(a));
    return __uint_as_float(lo) + __uint_as_float(hi);
}
__device__ __forceinline__ float sigmoidf_(float x) {
    return __fdividef(1.0f, 1.0f + __expf(-x));
}

// =====================================================================
// Kernel 1: gi = stimulus @ W_ih^T + b_ih — R15 lane-swapped version
// (w-loads 8-way broadcast: 1 wf; x-loads distinct rows: 1 wf).
// =====================================================================
#define GI_TBT 16
#define GI_PITCH 70
#define GI_SMEM ((G3 * GI_PITCH + GI_TBT * GI_PITCH) * 4)

__global__ void __launch_bounds__(512, 1)
gi_kernel(const float* __restrict__ stim,
          const float* __restrict__ W_ih,
          const float* __restrict__ b_ih)
{
    extern __shared__ float sm[];
    float* w_s = sm;                    // [768][70]
    float* x_s = sm + G3 * GI_PITCH;    // [16][70]

    const int tid = threadIdx.x;
    const int bt0 = blockIdx.x * GI_TBT;

    for (int idx = tid; idx < G3 * IN_DIM; idx += 512) {
        int g = idx / IN_DIM, k = idx - g * IN_DIM;
        w_s[g * GI_PITCH + k] = W_ih[idx];
    }
    for (int idx = tid; idx < GI_TBT * IN_DIM; idx += 512) {
        int r = idx / IN_DIM, c = idx - r * IN_DIM;
        x_s[r * GI_PITCH + c] = stim[(size_t)(bt0 + r) * IN_DIM + c];
    }
    __syncthreads();

    const int gx = tid >> 3;        // 0..63  (4 distinct per warp -> bcast w)
    const int by = tid & 7;         // 0..7   (lane-varying -> distinct x rows)

    unsigned long long acc0[12], acc1[12];
#pragma unroll
    for (int i = 0; i < 12; ++i) { acc0[i] = 0ull; acc1[i] = 0ull; }

    const float* x0 = x_s + (by * 2) * GI_PITCH;
    const float* x1 = x_s + (by * 2 + 1) * GI_PITCH;

#pragma unroll 4
    for (int k = 0; k < 64; k += 2) {
        unsigned long long xv0 = *(const unsigned long long*)(x0 + k);
        unsigned long long xv1 = *(const unsigned long long*)(x1 + k);
#pragma unroll
        for (int i = 0; i < 12; ++i) {
            unsigned long long wv =
                *(const unsigned long long*)(w_s + (gx + 64 * i) * GI_PITCH + k);
            ffma2(acc0[i], xv0, wv);
            ffma2(acc1[i], xv1, wv);
        }
    }
    const float x0l = x0[64], x1l = x1[64];

    const size_t base0 = (size_t)(bt0 + by * 2) * G3;
    const size_t base1 = base0 + G3;
#pragma unroll
    for (int i = 0; i < 12; ++i) {
        int   g    = gx + 64 * i;
        float w64  = w_s[g * GI_PITCH + 64];
        float bias = b_ih[g];
        g_gi[base0 + g] = f2sum(acc0[i]) + x0l * w64 + bias;
        g_gi[base1 + g] = f2sum(acc1[i]) + x1l * w64 + bias;
    }
}

// =====================================================================
// Kernel 2: GRU — R7 body with the MEASURED-BEST epilogue (STG between
// cluster arrive/wait, −123us) + next-step gi prefetch also moved under
// the barrier shadow.
// =====================================================================
#define CLUSTER 4
#define HT 64
#define BT 8
#define WPITCH 260
#define HPITCH 260
#define GRU_SMEM ((3 * HT * WPITCH + 2 * BT * HPITCH) * 4)

__global__ void __cluster_dims__(CLUSTER, 1, 1) __launch_bounds__(256, 1)
gru_kernel(const float* __restrict__ W_hh,
           const float* __restrict__ b_hh,
           float* __restrict__ out_hid)
{
    extern __shared__ float smem[];
    float* Ws = smem;                   // [3][64][260]
    float* hs = smem + 3 * HT * WPITCH; // [2][8][260]

    const int tid = threadIdx.x;
    unsigned int rank;
    asm("mov.u32 %0, %%cluster_ctarank;" : "=r"(rank));
    const int cl     = blockIdx.x / CLUSTER;
    const int h_off  = (int)rank * HT;
    const int b_base = cl * BT;

    for (int idx = tid; idx < 3 * HT * HID; idx += 256) {
        int g   = idx >> 14;
        int rem = idx & 16383;
        int u   = rem >> 8;
        int k   = rem & 255;
        Ws[(g * HT + u) * WPITCH + k] = W_hh[((g * HID) + h_off + u) * HID + k];
    }
    for (int idx = tid; idx < BT * HID; idx += 256) {
        int b = idx >> 8, c = idx & 255;
        hs[b * HPITCH + c] = 0.1f;
    }
    __syncthreads();

    const int bx = tid & 3;
    const int u  = tid >> 2;
    const int b0 = 2 * bx, b1 = 2 * bx + 1;
    const int ug = h_off + u;

    const float bhr = b_hh[ug];
    const float bhz = b_hh[HID + ug];
    const float bhn = b_hh[2 * HID + ug];

    const float* gi0 = g_gi + (size_t)(b_base + b0) * SEQ * G3 + ug;
    const float* gi1 = g_gi + (size_t)(b_base + b1) * SEQ * G3 + ug;
    float* o0 = out_hid + (size_t)(b_base + b0) * SEQ * HID + ug;
    float* o1 = out_hid + (size_t)(b_base + b1) * SEQ * HID + ug;

    const unsigned int hs_u32 = (unsigned int)__cvta_generic_to_shared(hs);

    const float* w_r = Ws + (0 * HT + u) * WPITCH;
    const float* w_z = Ws + (1 * HT + u) * WPITCH;
    const float* w_n = Ws + (2 * HT + u) * WPITCH;

    // prologue: gi for t=0
    float gir0 = gi0[0], giz0 = gi0[HID], gin0 = gi0[2 * HID];
    float gir1 = gi1[0], giz1 = gi1[HID], gin1 = gi1[2 * HID];
    gi0 += G3;  gi1 += G3;    // -> t+1

    int buf = 0;
    for (int t = 0; t < SEQ; ++t) {
        const float* hr0 = hs + (buf * BT + b0) * HPITCH;
        const float* hr1 = hs + (buf * BT + b1) * HPITCH;

        unsigned long long ar0 = 0, az0 = 0, an0 = 0;
        unsigned long long ar1 = 0, az1 = 0, an1 = 0;
#pragma unroll 8
        for (int k = 0; k < HID; k += 4) {
            ulonglong2 h0 = *(const ulonglong2*)(hr0 + k);
            ulonglong2 h1 = *(const ulonglong2*)(hr1 + k);
            ulonglong2 wr = *(const ulonglong2*)(w_r + k);
            ulonglong2 wz = *(const ulonglong2*)(w_z + k);
            ulonglong2 wn = *(const ulonglong2*)(w_n + k);
            ffma2(ar0, h0.x, wr.x); ffma2(ar0, h0.y, wr.y);
            ffma2(az0, h0.x, wz.x); ffma2(az0, h0.y, wz.y);
            ffma2(an0, h0.x, wn.x); ffma2(an0, h0.y, wn.y);
            ffma2(ar1, h1.x, wr.x); ffma2(ar1, h1.y, wr.y);
            ffma2(az1, h1.x, wz.x); ffma2(az1, h1.y, wz.y);
            ffma2(an1, h1.x, wn.x); ffma2(an1, h1.y, wn.y);
        }
        float sr0 = f2sum(ar0) + bhr, sz0 = f2sum(az0) + bhz, sn0 = f2sum(an0) + bhn;
        float sr1 = f2sum(ar1) + bhr, sz1 = f2sum(az1) + bhz, sn1 = f2sum(an1) + bhn;

        float h_old0 = hr0[ug];
        float h_old1 = hr1[ug];

        float r0 = sigmoidf_(gir0 + sr0);
        float z0 = sigmoidf_(giz0 + sz0);
        float n0 = fmaxf(fmaf(r0, sn0, gin0), 0.0f);
        float hn0 = fmaf(z0, h_old0 - n0, n0);      // (1-z)n + z*h

        float r1 = sigmoidf_(gir1 + sr1);
        float z1 = sigmoidf_(giz1 + sz1);
        float n1 = fmaxf(fmaf(r1, sn1, gin1), 0.0f);
        float hn1 = fmaf(z1, h_old1 - n1, n1);

        // DSMEM broadcast of new h into next buffer of ALL cluster CTAs
        const int nbuf = buf ^ 1;
        unsigned int a0 = hs_u32 + (unsigned int)(((nbuf * BT + b0) * HPITCH + ug) * 4);
        unsigned int a1 = hs_u32 + (unsigned int)(((nbuf * BT + b1) * HPITCH + ug) * 4);
#pragma unroll
        for (int rr = 0; rr < CLUSTER; ++rr) {
            unsigned int ra0, ra1;
            asm("mapa.shared::cluster.u32 %0, %1, %2;" : "=r"(ra0) : "r"(a0), "r"(rr));
            asm("mapa.shared::cluster.u32 %0, %1, %2;" : "=r"(ra1) : "r"(a1), "r"(rr));
            asm volatile("st.shared::cluster.f32 [%0], %1;" :: "r"(ra0), "f"(hn0) : "memory");
            asm volatile("st.shared::cluster.f32 [%0], %1;" :: "r"(ra1), "f"(hn1) : "memory");
        }
        asm volatile("barrier.cluster.arrive.aligned;" ::: "memory");

        // ---- work hidden under the barrier shadow ----
        o0[0] = hn0;               // measured: -123us vs before-arrive
        o1[0] = hn1;
        float ngir0 = 0.f, ngiz0 = 0.f, ngin0 = 0.f;
        float ngir1 = 0.f, ngiz1 = 0.f, ngin1 = 0.f;
        if (t + 1 < SEQ) {         // prefetch gi[t+1] under the barrier too
            ngir0 = gi0[0]; ngiz0 = gi0[HID]; ngin0 = gi0[2 * HID];
            ngir1 = gi1[0]; ngiz1 = gi1[HID]; ngin1 = gi1[2 * HID];
        }

        asm volatile("barrier.cluster.wait.aligned;" ::: "memory");

        gir0 = ngir0; giz0 = ngiz0; gin0 = ngin0;
        gir1 = ngir1; giz1 = ngiz1; gin1 = ngin1;
        buf = nbuf;
        gi0 += G3; gi1 += G3; o0 += HID; o1 += HID;
    }
}

// =====================================================================
// Kernel 3: head — R16 measured version (TBT=32, 2 CTAs/SM, 212us).
// =====================================================================
#define HD_TBT 32
#define HD_HPITCH 260
#define HD_WPITCH 258
#define HD_SMEM ((HD_TBT * HD_HPITCH + RDIM * HD_WPITCH) * 4)   // 99,328 B

__global__ void __launch_bounds__(256, 2)
head_kernel(const float* __restrict__ hid,
            const float* __restrict__ W_out,
            const float* __restrict__ b_out,
            float* __restrict__ out)
{
    extern __shared__ float sm[];
    float* h_s = sm;                      // [32][260]
    float* w_s = sm + HD_TBT * HD_HPITCH; // [64][258]

    const int tid = threadIdx.x;
    const int bt0 = blockIdx.x * HD_TBT;

    for (int idx = tid; idx < HD_TBT * HID; idx += 256) {
        int r = idx >> 8, c = idx & 255;
        h_s[r * HD_HPITCH + c] = hid[(size_t)(bt0 + r) * HID + c];
    }
    for (int idx = tid; idx < RDIM * HID; idx += 256) {
        int r = idx >> 8, c = idx & 255;
        w_s[r * HD_WPITCH + c] = W_out[idx];
    }
    __syncthreads();

    const int rx = tid & 15;   // r  = rx + 16*i, i < 4
    const int by = tid >> 4;   // bt = bt0 + by*2 + j, j < 2

    unsigned long long acc[2][4];
#pragma unroll
    for (int j = 0; j < 2; ++j)
#pragma unroll
        for (int i = 0; i < 4; ++i) acc[j][i] = 0ull;

#pragma unroll 4
    for (int k = 0; k < HID; k += 2) {
        unsigned long long hv[2], wv[4];
#pragma unroll
        for (int j = 0; j < 2; ++j)
            hv[j] = *(const unsigned long long*)(h_s + (by * 2 + j) * HD_HPITCH + k);
#pragma unroll
        for (int i = 0; i < 4; ++i)
            wv[i] = *(const unsigned long long*)(w_s + (rx + 16 * i) * HD_WPITCH + k);
#pragma unroll
        for (int j = 0; j < 2; ++j)
#pragma unroll
            for (int i = 0; i < 4; ++i) ffma2(acc[j][i], hv[j], wv[i]);
    }

#pragma unroll
    for (int j = 0; j < 2; ++j) {
        size_t row = (size_t)(bt0 + by * 2 + j) * RDIM;
#pragma unroll
        for (int i = 0; i < 4; ++i) {
            int   r = rx + 16 * i;
            float v = f2sum(acc[j][i]) + b_out[r];
            out[row + r] = fmaxf(v, 0.0f);
        }
    }
}

// =====================================================================
extern "C" void kernel_launch(void* const* d_in, const int* in_sizes, int n_in,
                              void* d_out, int out_size)
{
    const float *stim = nullptr, *W_ih = nullptr, *W_hh = nullptr,
                *b_ih = nullptr, *b_hh = nullptr, *W_out = nullptr, *b_out = nullptr;

    for (int i = 0; i < n_in; ++i) {
        const float* p = (const float*)d_in[i];
        switch (in_sizes[i]) {
            case BATCH * SEQ * IN_DIM: stim  = p; break;
            case G3 * IN_DIM:          W_ih  = p; break;
            case G3 * HID:             W_hh  = p; break;
            case RDIM * HID:           W_out = p; break;
            case RDIM:                 b_out = p; break;
            case G3:
                if (!b_ih) b_ih = p; else b_hh = p;
                break;
            default: break;
        }
    }
    if (!stim || !W_ih || !W_hh || !b_ih || !b_hh || !W_out || !b_out)
        return;

    float* g_hid_ptr;  cudaGetSymbolAddress((void**)&g_hid_ptr, g_hid);
    float* g_out_ptr;  cudaGetSymbolAddress((void**)&g_out_ptr, g_out);

    float* out;
    float* hid;
    if ((size_t)out_size >= TOT_N) {
        out = (float*)d_out;
        hid = (float*)d_out + OUT_N;
    } else if ((size_t)out_size >= HID_N) {
        hid = (float*)d_out;
        out = g_out_ptr;
    } else {
        out = (float*)d_out;
        hid = g_hid_ptr;
    }

    cudaFuncSetAttribute(gi_kernel,   cudaFuncAttributeMaxDynamicSharedMemorySize, GI_SMEM);
    cudaFuncSetAttribute(gru_kernel,  cudaFuncAttributeMaxDynamicSharedMemorySize, GRU_SMEM);
    cudaFuncSetAttribute(head_kernel, cudaFuncAttributeMaxDynamicSharedMemorySize, HD_SMEM);

    gi_kernel  <<<(BATCH * SEQ) / GI_TBT, 512, GI_SMEM>>>(stim, W_ih, b_ih);
    gru_kernel <<<(BATCH / BT) * CLUSTER, 256, GRU_SMEM>>>(W_hh, b_hh, hid);
    head_kernel<<<(BATCH * SEQ) / HD_TBT, 256, HD_SMEM>>>(hid, W_out, b_out, out);
}